// round 3
// baseline (speedup 1.0000x reference)
#include <cuda_runtime.h>
#include <cuda_bf16.h>
#include <math.h>
#include <stdint.h>

#define BATCH   16384
#define HID     1024
#define CTXK    512
#define N4      4096
#define TSTEPS  60
#define INW     516     // W_ih row width (C+4)

// gates GEMM geometry: x = [h(1024), extra(4), pad(28)] -> XKG=1056
#define XKG     1056
#define AGLD    (2*XKG)    // 2112  A_gates row width (hi|lo)
#define KG      (3*XKG)    // 3168
// ffn GEMM: x = y(1024)
#define XKF     1024
#define AFLD    (2*XKF)    // 2048
#define KF      (3*XKF)    // 3072
// context GEMMs: x = context(512)
#define XKC     512
#define ACLD    (2*XKC)    // 1024
#define KC      (3*XKC)    // 1536

// ------------------------- scratch (device globals) -------------------------
__device__ __align__(256) float          g_gctx[(size_t)BATCH * N4];          // 268MB
__device__ __align__(256) __nv_bfloat16  g_Ag0[(size_t)BATCH * AGLD];         // 69MB
__device__ __align__(256) __nv_bfloat16  g_Ag1[(size_t)BATCH * AGLD];         // 69MB
__device__ __align__(256) __nv_bfloat16  g_Af [(size_t)BATCH * AFLD];         // 67MB
__device__ __align__(256) __nv_bfloat16  g_ctxs[(size_t)BATCH * ACLD];        // 33MB
__device__ __align__(256) float          g_c  [(size_t)BATCH * HID];          // 67MB
__device__ __align__(256) float          g_y2 [(size_t)BATCH * HID];          // 67MB
__device__ __align__(256) float          g_pos[(size_t)BATCH * 2];
__device__ __align__(256) __nv_bfloat16  g_Wg  [(size_t)N4 * KG];             // 26MB
__device__ __align__(256) __nv_bfloat16  g_Wc4 [(size_t)N4 * KC];             // 13MB
__device__ __align__(256) __nv_bfloat16  g_Whh [(size_t)HID * KC];            // 3MB
__device__ __align__(256) __nv_bfloat16  g_Wcc [(size_t)HID * KC];            // 3MB
__device__ __align__(256) __nv_bfloat16  g_W1s [(size_t)HID * KF];            // 6MB
__device__ __align__(256) float          g_bsum[N4];

// ------------------------- prep kernels -------------------------
__global__ void prep_ctx_split(const float* __restrict__ ctx) {
    int i = blockIdx.x * blockDim.x + threadIdx.x;
    if (i >= BATCH * CTXK) return;
    int b = i / CTXK, k = i % CTXK;
    float v = ctx[i];
    __nv_bfloat16 hi = __float2bfloat16(v);
    float lo = v - __bfloat162float(hi);
    g_ctxs[(size_t)b * ACLD + k]       = hi;
    g_ctxs[(size_t)b * ACLD + XKC + k] = __float2bfloat16(lo);
}

// W_gates: rows permuted n' = 4*j + gate ; cols [W_hh(1024), W_extra(4), 0-pad]
__global__ void prep_wgates(const float* __restrict__ Whh, const float* __restrict__ Wih) {
    int i = blockIdx.x * blockDim.x + threadIdx.x;
    if (i >= N4 * XKG) return;
    int np = i / XKG, k = i % XKG;
    int r = (np & 3) * HID + (np >> 2);
    float w = 0.f;
    if (k < HID)            w = Whh[(size_t)r * HID + k];
    else if (k < HID + 4)   w = Wih[(size_t)r * INW + CTXK + (k - HID)];
    __nv_bfloat16 hi = __float2bfloat16(w);
    float lo = w - __bfloat162float(hi);
    size_t base = (size_t)np * KG;
    g_Wg[base + k]           = hi;
    g_Wg[base + XKG + k]     = hi;
    g_Wg[base + 2 * XKG + k] = __float2bfloat16(lo);
}

__global__ void prep_wctx(const float* __restrict__ Wih) {
    int i = blockIdx.x * blockDim.x + threadIdx.x;
    if (i >= N4 * XKC) return;
    int np = i / XKC, k = i % XKC;
    int r = (np & 3) * HID + (np >> 2);
    float w = Wih[(size_t)r * INW + k];
    __nv_bfloat16 hi = __float2bfloat16(w);
    float lo = w - __bfloat162float(hi);
    size_t base = (size_t)np * KC;
    g_Wc4[base + k]           = hi;
    g_Wc4[base + XKC + k]     = hi;
    g_Wc4[base + 2 * XKC + k] = __float2bfloat16(lo);
}

__global__ void prep_bsum(const float* __restrict__ b_ih, const float* __restrict__ b_hh) {
    int np = blockIdx.x * blockDim.x + threadIdx.x;
    if (np >= N4) return;
    int r = (np & 3) * HID + (np >> 2);
    g_bsum[np] = b_ih[r] + b_hh[r];
}

// generic split (srcld == xk): out[r][3*xk] = [hi|hi|lo]
__global__ void prep_split3(const float* __restrict__ W, __nv_bfloat16* __restrict__ o,
                            int total, int xk) {
    int i = blockIdx.x * blockDim.x + threadIdx.x;
    if (i >= total) return;
    int r = i / xk, k = i % xk;
    float w = W[(size_t)r * xk + k];
    __nv_bfloat16 hi = __float2bfloat16(w);
    float lo = w - __bfloat162float(hi);
    size_t base = (size_t)r * (3 * xk);
    o[base + k]          = hi;
    o[base + xk + k]     = hi;
    o[base + 2 * xk + k] = __float2bfloat16(lo);
}

__global__ void init_misc(const float* __restrict__ last_pos, const float* __restrict__ last_delta) {
    int b = blockIdx.x * blockDim.x + threadIdx.x;
    if (b >= BATCH) return;
    g_pos[b * 2 + 0] = last_pos[b * 2 + 0];
    g_pos[b * 2 + 1] = last_pos[b * 2 + 1];
    float d0 = last_delta[b * 2 + 0], d1 = last_delta[b * 2 + 1];
    float nn = fmaxf(sqrtf(d0 * d0 + d1 * d1), 1e-6f);
    float e[4] = {d0, d1, d0 / nn, d1 / nn};
    size_t base = (size_t)b * AGLD;
#pragma unroll
    for (int q = 0; q < 4; q++) {
        __nv_bfloat16 hi = __float2bfloat16(e[q]);
        float lo = e[q] - __bfloat162float(hi);
        g_Ag0[base + HID + q]       = hi;
        g_Ag0[base + XKG + HID + q] = __float2bfloat16(lo);
    }
    __nv_bfloat16 z = __float2bfloat16(0.f);
    for (int k = HID + 4; k < XKG; k++) {
        g_Ag0[base + k] = z; g_Ag0[base + XKG + k] = z;
        g_Ag1[base + k] = z; g_Ag1[base + XKG + k] = z;
    }
}

// ------------------------- GEMM (mma.sync bf16 3-split) -------------------------
#define MT 128
#define NT 128
#define KTILE 32

enum { EPI_CTX = 0, EPI_TANH_SPLIT = 1, EPI_TANH_C = 2, EPI_GATES = 3, EPI_GELU = 4 };

__device__ __forceinline__ void mma16816(float* c, const uint32_t* a, const uint32_t* b) {
    asm volatile(
        "mma.sync.aligned.m16n8k16.row.col.f32.bf16.bf16.f32 "
        "{%0,%1,%2,%3},{%4,%5,%6,%7},{%8,%9},{%0,%1,%2,%3};\n"
        : "+f"(c[0]), "+f"(c[1]), "+f"(c[2]), "+f"(c[3])
        : "r"(a[0]), "r"(a[1]), "r"(a[2]), "r"(a[3]), "r"(b[0]), "r"(b[1]));
}

__device__ __forceinline__ void lstm_cell(float* cbuf, __nv_bfloat16* outs, int row, int j,
                                          float gi, float gf, float gg, float go) {
    float cold = cbuf[(size_t)row * HID + j];
    float si = 1.f / (1.f + expf(-gi));
    float sf = 1.f / (1.f + expf(-gf));
    float so = 1.f / (1.f + expf(-go));
    float tg = tanhf(gg);
    float cn = sf * cold + si * tg;
    float h  = so * tanhf(cn);
    cbuf[(size_t)row * HID + j] = cn;
    __nv_bfloat16 hi = __float2bfloat16(h);
    outs[(size_t)row * AGLD + j]       = hi;
    outs[(size_t)row * AGLD + XKG + j] = __float2bfloat16(h - __bfloat162float(hi));
}

template <int EPI>
__global__ void __launch_bounds__(256, 2)
gemm_k(const __nv_bfloat16* __restrict__ A, int ldA,
       const __nv_bfloat16* __restrict__ W, int ktot,
       const float* __restrict__ aux,        // bias[n], or gctx[r][N4] for EPI_GATES
       float* __restrict__ outf,             // c / y2 / gctx
       __nv_bfloat16* __restrict__ outs,     // split target (A_gates)
       int nOut) {
    __shared__ __align__(16) __nv_bfloat16 As[2][MT][KTILE + 8];
    __shared__ __align__(16) __nv_bfloat16 Bs[2][NT][KTILE + 8];

    const int tid = threadIdx.x;
    const int m0 = blockIdx.y * MT, n0 = blockIdx.x * NT;
    const int wid = tid >> 5, lane = tid & 31;
    const int wm = wid >> 2, wn = wid & 3;

    float acc[4][4][4];
#pragma unroll
    for (int a = 0; a < 4; a++)
#pragma unroll
        for (int b = 0; b < 4; b++)
#pragma unroll
            for (int c = 0; c < 4; c++) acc[a][b][c] = 0.f;

    const int nK = ktot / KTILE;

    auto loadst = [&](int st, int k0) {
#pragma unroll
        for (int t = 0; t < 2; t++) {
            int c = tid + t * 256;
            int row = c >> 2, kc = (c & 3) * 8;
            int gk = k0 + kc;
            int col = gk < ldA ? gk : gk - ldA;   // 3rd segment re-reads hi
            const __nv_bfloat16* src = A + (size_t)(m0 + row) * ldA + col;
            uint32_t dst = (uint32_t)__cvta_generic_to_shared(&As[st][row][kc]);
            asm volatile("cp.async.cg.shared.global [%0],[%1],16;\n" ::"r"(dst), "l"(src));
        }
#pragma unroll
        for (int t = 0; t < 2; t++) {
            int c = tid + t * 256;
            int row = c >> 2, kc = (c & 3) * 8;
            const __nv_bfloat16* src = W + (size_t)(n0 + row) * ktot + k0 + kc;
            uint32_t dst = (uint32_t)__cvta_generic_to_shared(&Bs[st][row][kc]);
            asm volatile("cp.async.cg.shared.global [%0],[%1],16;\n" ::"r"(dst), "l"(src));
        }
        asm volatile("cp.async.commit_group;\n");
    };

    loadst(0, 0);
    for (int kt = 0; kt < nK; kt++) {
        if (kt + 1 < nK) {
            loadst((kt + 1) & 1, (kt + 1) * KTILE);
            asm volatile("cp.async.wait_group 1;\n");
        } else {
            asm volatile("cp.async.wait_group 0;\n");
        }
        __syncthreads();
        const int st = kt & 1;
#pragma unroll
        for (int kk = 0; kk < 2; kk++) {
            uint32_t a[4][4], b[4][2];
            const int kb = kk * 16 + (lane & 3) * 2;
#pragma unroll
            for (int mt = 0; mt < 4; mt++) {
                int r = wm * 64 + mt * 16 + (lane >> 2);
                a[mt][0] = *(const uint32_t*)&As[st][r][kb];
                a[mt][1] = *(const uint32_t*)&As[st][r + 8][kb];
                a[mt][2] = *(const uint32_t*)&As[st][r][kb + 8];
                a[mt][3] = *(const uint32_t*)&As[st][r + 8][kb + 8];
            }
#pragma unroll
            for (int nt = 0; nt < 4; nt++) {
                int c2 = wn * 32 + nt * 8 + (lane >> 2);
                b[nt][0] = *(const uint32_t*)&Bs[st][c2][kb];
                b[nt][1] = *(const uint32_t*)&Bs[st][c2][kb + 8];
            }
#pragma unroll
            for (int mt = 0; mt < 4; mt++)
#pragma unroll
                for (int nt = 0; nt < 4; nt++) mma16816(acc[mt][nt], a[mt], b[nt]);
        }
        __syncthreads();
    }

    // ------------------------- epilogue -------------------------
#pragma unroll
    for (int mt = 0; mt < 4; mt++) {
#pragma unroll
        for (int nt = 0; nt < 4; nt++) {
            int r = m0 + wm * 64 + mt * 16 + (lane >> 2);
            int n = n0 + wn * 32 + nt * 8 + (lane & 3) * 2;
            float v0 = acc[mt][nt][0], v1 = acc[mt][nt][1];
            float v2 = acc[mt][nt][2], v3 = acc[mt][nt][3];

            if (EPI == EPI_CTX) {
                outf[(size_t)r * nOut + n]           = v0 + aux[n];
                outf[(size_t)r * nOut + n + 1]       = v1 + aux[n + 1];
                outf[(size_t)(r + 8) * nOut + n]     = v2 + aux[n];
                outf[(size_t)(r + 8) * nOut + n + 1] = v3 + aux[n + 1];
            } else if (EPI == EPI_TANH_C) {
                outf[(size_t)r * nOut + n]           = tanhf(v0 + aux[n]);
                outf[(size_t)r * nOut + n + 1]       = tanhf(v1 + aux[n + 1]);
                outf[(size_t)(r + 8) * nOut + n]     = tanhf(v2 + aux[n]);
                outf[(size_t)(r + 8) * nOut + n + 1] = tanhf(v3 + aux[n + 1]);
            } else if (EPI == EPI_TANH_SPLIT) {
#pragma unroll
                for (int q = 0; q < 4; q++) {
                    int rr = (q >= 2) ? r + 8 : r;
                    int nn = n + (q & 1);
                    float v = (q == 0) ? v0 : (q == 1) ? v1 : (q == 2) ? v2 : v3;
                    float h = tanhf(v + aux[nn]);
                    __nv_bfloat16 hi = __float2bfloat16(h);
                    outs[(size_t)rr * AGLD + nn]       = hi;
                    outs[(size_t)rr * AGLD + XKG + nn] = __float2bfloat16(h - __bfloat162float(hi));
                }
            } else if (EPI == EPI_GELU) {
#pragma unroll
                for (int q = 0; q < 4; q++) {
                    int rr = (q >= 2) ? r + 8 : r;
                    int nn = n + (q & 1);
                    float v = (q == 0) ? v0 : (q == 1) ? v1 : (q == 2) ? v2 : v3;
                    float u = v + aux[nn];
                    outf[(size_t)rr * nOut + nn] = 0.5f * u * (1.f + erff(u * 0.70710678118654752f));
                }
            } else { // EPI_GATES
                float w0 = v0 + aux[(size_t)r * N4 + n];
                float w1 = v1 + aux[(size_t)r * N4 + n + 1];
                float w2 = v2 + aux[(size_t)(r + 8) * N4 + n];
                float w3 = v3 + aux[(size_t)(r + 8) * N4 + n + 1];
                float u0 = __shfl_xor_sync(0xffffffffu, w0, 1);
                float u1 = __shfl_xor_sync(0xffffffffu, w1, 1);
                float u2 = __shfl_xor_sync(0xffffffffu, w2, 1);
                float u3 = __shfl_xor_sync(0xffffffffu, w3, 1);
                if (!(lane & 1)) {  // n % 4 == 0: owns (i,f), partner has (g,o)
                    int j = n >> 2;
                    lstm_cell(outf, outs, r, j, w0, w1, u0, u1);
                    lstm_cell(outf, outs, r + 8, j, w2, w3, u2, u3);
                }
            }
        }
    }
}

// ------------------------- LayerNorm (warp per row) -------------------------
__global__ void ln_kernel(const __nv_bfloat16* __restrict__ Ag,
                          const float* __restrict__ gam, const float* __restrict__ bet) {
    int warp = (blockIdx.x * blockDim.x + threadIdx.x) >> 5;
    int lane = threadIdx.x & 31;
    if (warp >= BATCH) return;
    size_t base = (size_t)warp * AGLD;
    float h[32];
    float s = 0.f, ss = 0.f;
#pragma unroll
    for (int i = 0; i < 32; i++) {
        int k = lane + 32 * i;
        float v = __bfloat162float(Ag[base + k]) + __bfloat162float(Ag[base + XKG + k]);
        h[i] = v; s += v; ss += v * v;
    }
#pragma unroll
    for (int o = 16; o; o >>= 1) {
        s  += __shfl_xor_sync(0xffffffffu, s, o);
        ss += __shfl_xor_sync(0xffffffffu, ss, o);
    }
    float mu = s * (1.f / HID);
    float var = ss * (1.f / HID) - mu * mu;
    float inv = rsqrtf(var + 1e-5f);
    size_t ob = (size_t)warp * AFLD;
#pragma unroll
    for (int i = 0; i < 32; i++) {
        int k = lane + 32 * i;
        float y = (h[i] - mu) * inv * gam[k] + bet[k];
        __nv_bfloat16 hi = __float2bfloat16(y);
        g_Af[ob + k]       = hi;
        g_Af[ob + XKF + k] = __float2bfloat16(y - __bfloat162float(hi));
    }
}

// ------------------------- delta / pos head (warp per row) -------------------------
__global__ void delta_kernel(const float* __restrict__ W2, const float* __restrict__ b2,
                             float* __restrict__ out, int t, __nv_bfloat16* __restrict__ AgN) {
    int warp = (blockIdx.x * blockDim.x + threadIdx.x) >> 5;
    int lane = threadIdx.x & 31;
    if (warp >= BATCH) return;
    const float* y = g_y2 + (size_t)warp * HID;
    float a0 = 0.f, a1 = 0.f;
#pragma unroll
    for (int i = 0; i < 32; i++) {
        int k = lane + 32 * i;
        float v = y[k];
        a0 += v * W2[k];
        a1 += v * W2[HID + k];
    }
#pragma unroll
    for (int o = 16; o; o >>= 1) {
        a0 += __shfl_xor_sync(0xffffffffu, a0, o);
        a1 += __shfl_xor_sync(0xffffffffu, a1, o);
    }
    if (lane == 0) {
        float d0 = a0 + b2[0], d1 = a1 + b2[1];
        float p0 = g_pos[warp * 2 + 0] + d0;
        float p1 = g_pos[warp * 2 + 1] + d1;
        g_pos[warp * 2 + 0] = p0;
        g_pos[warp * 2 + 1] = p1;
        out[(size_t)warp * (TSTEPS * 2) + t * 2 + 0] = p0;
        out[(size_t)warp * (TSTEPS * 2) + t * 2 + 1] = p1;
        float nn = fmaxf(sqrtf(d0 * d0 + d1 * d1), 1e-6f);
        float e[4] = {d0, d1, d0 / nn, d1 / nn};
        size_t base = (size_t)warp * AGLD;
#pragma unroll
        for (int q = 0; q < 4; q++) {
            __nv_bfloat16 hi = __float2bfloat16(e[q]);
            AgN[base + HID + q]       = hi;
            AgN[base + XKG + HID + q] = __float2bfloat16(e[q] - __bfloat162float(hi));
        }
    }
}

// ------------------------- host -------------------------
static inline int nb(long n) { return (int)((n + 255) / 256); }

extern "C" void kernel_launch(void* const* d_in, const int* in_sizes, int n_in,
                              void* d_out, int out_size) {
    const float* context    = (const float*)d_in[0];
    const float* last_pos   = (const float*)d_in[1];
    const float* last_delta = (const float*)d_in[2];
    const float* Wh   = (const float*)d_in[3];
    const float* bh   = (const float*)d_in[4];
    const float* Wc   = (const float*)d_in[5];
    const float* bc   = (const float*)d_in[6];
    const float* W_ih = (const float*)d_in[7];
    const float* b_ih = (const float*)d_in[8];
    const float* W_hh = (const float*)d_in[9];
    const float* b_hh = (const float*)d_in[10];
    const float* ln_g = (const float*)d_in[11];
    const float* ln_b = (const float*)d_in[12];
    const float* W1   = (const float*)d_in[13];
    const float* b1   = (const float*)d_in[14];
    const float* W2   = (const float*)d_in[15];
    const float* b2   = (const float*)d_in[16];
    float* out = (float*)d_out;

    __nv_bfloat16 *pCtxs, *pAg0, *pAg1, *pAf, *pWg, *pWc4, *pWhh, *pWcc, *pW1s;
    float *pGctx, *pC, *pY2, *pBsum;
    cudaGetSymbolAddress((void**)&pCtxs, g_ctxs);
    cudaGetSymbolAddress((void**)&pAg0, g_Ag0);
    cudaGetSymbolAddress((void**)&pAg1, g_Ag1);
    cudaGetSymbolAddress((void**)&pAf,  g_Af);
    cudaGetSymbolAddress((void**)&pWg,  g_Wg);
    cudaGetSymbolAddress((void**)&pWc4, g_Wc4);
    cudaGetSymbolAddress((void**)&pWhh, g_Whh);
    cudaGetSymbolAddress((void**)&pWcc, g_Wcc);
    cudaGetSymbolAddress((void**)&pW1s, g_W1s);
    cudaGetSymbolAddress((void**)&pGctx, g_gctx);
    cudaGetSymbolAddress((void**)&pC,   g_c);
    cudaGetSymbolAddress((void**)&pY2,  g_y2);
    cudaGetSymbolAddress((void**)&pBsum, g_bsum);

    // prep
    prep_ctx_split<<<nb((long)BATCH * CTXK), 256>>>(context);
    prep_wgates<<<nb((long)N4 * XKG), 256>>>(W_hh, W_ih);
    prep_wctx<<<nb((long)N4 * XKC), 256>>>(W_ih);
    prep_bsum<<<nb(N4), 256>>>(b_ih, b_hh);
    prep_split3<<<nb((long)HID * XKC), 256>>>(Wh, pWhh, HID * XKC, XKC);
    prep_split3<<<nb((long)HID * XKC), 256>>>(Wc, pWcc, HID * XKC, XKC);
    prep_split3<<<nb((long)HID * HID), 256>>>(W1, pW1s, HID * HID, HID);
    init_misc<<<nb(BATCH), 256>>>(last_pos, last_delta);

    dim3 blk(256);
    dim3 grid_n4(N4 / NT, BATCH / MT);
    dim3 grid_h(HID / NT, BATCH / MT);

    // gates_ctx (permuted, + b_ih + b_hh)
    gemm_k<EPI_CTX><<<grid_n4, blk>>>(pCtxs, ACLD, pWc4, KC, pBsum, pGctx, nullptr, N4);
    // hidden / cell init
    gemm_k<EPI_TANH_SPLIT><<<grid_h, blk>>>(pCtxs, ACLD, pWhh, KC, bh, nullptr, pAg0, HID);
    gemm_k<EPI_TANH_C><<<grid_h, blk>>>(pCtxs, ACLD, pWcc, KC, bc, pC, nullptr, HID);

    __nv_bfloat16* Ag[2] = {pAg0, pAg1};
    for (int t = 0; t < TSTEPS; t++) {
        int cur = t & 1, nxt = cur ^ 1;
        gemm_k<EPI_GATES><<<grid_n4, blk>>>(Ag[cur], AGLD, pWg, KG, pGctx, pC, Ag[nxt], N4);
        ln_kernel<<<BATCH / 8, 256>>>(Ag[nxt], ln_g, ln_b);
        gemm_k<EPI_GELU><<<grid_h, blk>>>(pAf, AFLD, pW1s, KF, b1, pY2, nullptr, HID);
        delta_kernel<<<BATCH / 8, 256>>>(W2, b2, out, t, Ag[nxt]);
    }
}

// round 6
// speedup vs baseline: 1.4268x; 1.4268x over previous
#include <cuda_runtime.h>
#include <cuda_bf16.h>
#include <math.h>
#include <stdint.h>

#define BATCH   16384
#define HID     1024
#define CTXK    512
#define N4      4096
#define TSTEPS  60
#define INW     516     // W_ih row width (C+4)

// gates GEMM: x = [h(1024), extra(4), pad(60)] -> XKG=1088 (multiple of 64)
#define XKG     1088
#define AGLD    (2*XKG)    // 2176  A_gates row width (hi|lo)
#define KG      (3*XKG)    // 3264 = 51*64
// ffn GEMM: x = y(1024)
#define XKF     1024
#define AFLD    (2*XKF)    // 2048
#define KF      (3*XKF)    // 3072 = 48*64
// context GEMMs: x = context(512)
#define XKC     512
#define ACLD    (2*XKC)    // 1024
#define KC      (3*XKC)    // 1536

// ------------------------- scratch (device globals) -------------------------
__device__ __align__(256) float          g_gctx[(size_t)BATCH * N4];
__device__ __align__(256) __nv_bfloat16  g_Ag0[(size_t)BATCH * AGLD];
__device__ __align__(256) __nv_bfloat16  g_Ag1[(size_t)BATCH * AGLD];
__device__ __align__(256) __nv_bfloat16  g_Af [(size_t)BATCH * AFLD];
__device__ __align__(256) __nv_bfloat16  g_ctxs[(size_t)BATCH * ACLD];
__device__ __align__(256) float          g_c  [(size_t)BATCH * HID];
__device__ __align__(256) float          g_y2 [(size_t)BATCH * HID];
__device__ __align__(256) float          g_pos[(size_t)BATCH * 2];
__device__ __align__(256) __nv_bfloat16  g_Wg  [(size_t)N4 * KG];
__device__ __align__(256) __nv_bfloat16  g_Wc4 [(size_t)N4 * KC];
__device__ __align__(256) __nv_bfloat16  g_Whh [(size_t)HID * KC];
__device__ __align__(256) __nv_bfloat16  g_Wcc [(size_t)HID * KC];
__device__ __align__(256) __nv_bfloat16  g_W1s [(size_t)HID * KF];
__device__ __align__(256) float          g_bsum[N4];

// ------------------------- low-level helpers -------------------------
#define SW128(b) ((b) ^ (((b) >> 3) & 0x70))

__device__ __forceinline__ void cpasync16(uint32_t dst, const void* src) {
    asm volatile("cp.async.cg.shared.global [%0],[%1],16;\n" :: "r"(dst), "l"(src));
}
__device__ __forceinline__ void ldsm4(uint32_t* r, uint32_t addr) {
    asm volatile("ldmatrix.sync.aligned.m8n8.x4.shared.b16 {%0,%1,%2,%3}, [%4];"
                 : "=r"(r[0]), "=r"(r[1]), "=r"(r[2]), "=r"(r[3]) : "r"(addr));
}
__device__ __forceinline__ void mma16816(float* c, const uint32_t* a, const uint32_t* b) {
    asm volatile(
        "mma.sync.aligned.m16n8k16.row.col.f32.bf16.bf16.f32 "
        "{%0,%1,%2,%3},{%4,%5,%6,%7},{%8,%9},{%0,%1,%2,%3};\n"
        : "+f"(c[0]), "+f"(c[1]), "+f"(c[2]), "+f"(c[3])
        : "r"(a[0]), "r"(a[1]), "r"(a[2]), "r"(a[3]), "r"(b[0]), "r"(b[1]));
}

// ------------------------- prep kernels -------------------------
__global__ void prep_ctx_split(const float* __restrict__ ctx) {
    int i = blockIdx.x * blockDim.x + threadIdx.x;
    if (i >= BATCH * CTXK) return;
    int b = i / CTXK, k = i % CTXK;
    float v = ctx[i];
    __nv_bfloat16 hi = __float2bfloat16(v);
    float lo = v - __bfloat162float(hi);
    g_ctxs[(size_t)b * ACLD + k]       = hi;
    g_ctxs[(size_t)b * ACLD + XKC + k] = __float2bfloat16(lo);
}

__global__ void prep_wgates(const float* __restrict__ Whh, const float* __restrict__ Wih) {
    int i = blockIdx.x * blockDim.x + threadIdx.x;
    if (i >= N4 * XKG) return;
    int np = i / XKG, k = i % XKG;
    int r = (np & 3) * HID + (np >> 2);
    float w = 0.f;
    if (k < HID)            w = Whh[(size_t)r * HID + k];
    else if (k < HID + 4)   w = Wih[(size_t)r * INW + CTXK + (k - HID)];
    __nv_bfloat16 hi = __float2bfloat16(w);
    float lo = w - __bfloat162float(hi);
    size_t base = (size_t)np * KG;
    g_Wg[base + k]           = hi;
    g_Wg[base + XKG + k]     = hi;
    g_Wg[base + 2 * XKG + k] = __float2bfloat16(lo);
}

__global__ void prep_wctx(const float* __restrict__ Wih) {
    int i = blockIdx.x * blockDim.x + threadIdx.x;
    if (i >= N4 * XKC) return;
    int np = i / XKC, k = i % XKC;
    int r = (np & 3) * HID + (np >> 2);
    float w = Wih[(size_t)r * INW + k];
    __nv_bfloat16 hi = __float2bfloat16(w);
    float lo = w - __bfloat162float(hi);
    size_t base = (size_t)np * KC;
    g_Wc4[base + k]           = hi;
    g_Wc4[base + XKC + k]     = hi;
    g_Wc4[base + 2 * XKC + k] = __float2bfloat16(lo);
}

__global__ void prep_bsum(const float* __restrict__ b_ih, const float* __restrict__ b_hh) {
    int np = blockIdx.x * blockDim.x + threadIdx.x;
    if (np >= N4) return;
    int r = (np & 3) * HID + (np >> 2);
    g_bsum[np] = b_ih[r] + b_hh[r];
}

__global__ void prep_split3(const float* __restrict__ W, __nv_bfloat16* __restrict__ o,
                            int total, int xk) {
    int i = blockIdx.x * blockDim.x + threadIdx.x;
    if (i >= total) return;
    int r = i / xk, k = i % xk;
    float w = W[(size_t)r * xk + k];
    __nv_bfloat16 hi = __float2bfloat16(w);
    float lo = w - __bfloat162float(hi);
    size_t base = (size_t)r * (3 * xk);
    o[base + k]          = hi;
    o[base + xk + k]     = hi;
    o[base + 2 * xk + k] = __float2bfloat16(lo);
}

__global__ void init_misc(const float* __restrict__ last_pos, const float* __restrict__ last_delta) {
    int b = blockIdx.x * blockDim.x + threadIdx.x;
    if (b >= BATCH) return;
    g_pos[b * 2 + 0] = last_pos[b * 2 + 0];
    g_pos[b * 2 + 1] = last_pos[b * 2 + 1];
    float d0 = last_delta[b * 2 + 0], d1 = last_delta[b * 2 + 1];
    float nn = fmaxf(sqrtf(d0 * d0 + d1 * d1), 1e-6f);
    float e[4] = {d0, d1, d0 / nn, d1 / nn};
    size_t base = (size_t)b * AGLD;
#pragma unroll
    for (int q = 0; q < 4; q++) {
        __nv_bfloat16 hi = __float2bfloat16(e[q]);
        float lo = e[q] - __bfloat162float(hi);
        g_Ag0[base + HID + q]       = hi;
        g_Ag0[base + XKG + HID + q] = __float2bfloat16(lo);
    }
    __nv_bfloat16 z = __float2bfloat16(0.f);
    for (int k = HID + 4; k < XKG; k++) {
        g_Ag0[base + k] = z; g_Ag0[base + XKG + k] = z;
        g_Ag1[base + k] = z; g_Ag1[base + XKG + k] = z;
    }
}

// ------------------------- GEMM engine v2 -------------------------
// 128x128 CTA tile, KTILE=64, 3-slot ring w/ 2 tiles in flight,
// ldmatrix fragments, one __syncthreads per K-tile.
// 256 threads, warp grid 2(M)x4(N), warp tile 64x32.
#define TK 64
#define NSTG 3
#define STG_BYTES 32768          // A 16KB + B 16KB
#define GEMM_SMEM (NSTG * STG_BYTES)

enum { EPI_CTX = 0, EPI_TANH_SPLIT = 1, EPI_TANH_C = 2, EPI_GATES = 3, EPI_GELU = 4 };

__device__ __forceinline__ void lstm_cell(float* cbuf, __nv_bfloat16* outs, int row, int j,
                                          float gi, float gf, float gg, float go) {
    float cold = cbuf[(size_t)row * HID + j];
    float si = 1.f / (1.f + expf(-gi));
    float sf = 1.f / (1.f + expf(-gf));
    float so = 1.f / (1.f + expf(-go));
    float tg = tanhf(gg);
    float cn = sf * cold + si * tg;
    float h  = so * tanhf(cn);
    cbuf[(size_t)row * HID + j] = cn;
    __nv_bfloat16 hi = __float2bfloat16(h);
    outs[(size_t)row * AGLD + j]       = hi;
    outs[(size_t)row * AGLD + XKG + j] = __float2bfloat16(h - __bfloat162float(hi));
}

template <int EPI>
__global__ void __launch_bounds__(256, 2)
gemm2(const __nv_bfloat16* __restrict__ A, int ldA,
      const __nv_bfloat16* __restrict__ W, int ktot,
      const float* __restrict__ aux,        // bias[n], or gctx for EPI_GATES
      float* __restrict__ outf,             // c / y2 / gctx
      __nv_bfloat16* __restrict__ outs,     // split target (A_gates / Ag0)
      int nOut) {
    extern __shared__ __align__(1024) char smp[];
    const uint32_t sbase = (uint32_t)__cvta_generic_to_shared(smp);

    const int tid = threadIdx.x;
    const int lane = tid & 31, wid = tid >> 5;
    const int wm = wid >> 2, wn = wid & 3;
    const int m0 = blockIdx.y * 128, n0 = blockIdx.x * 128;
    const int nK = ktot / TK;

    float acc[4][4][4];
#pragma unroll
    for (int a = 0; a < 4; a++)
#pragma unroll
        for (int b = 0; b < 4; b++)
#pragma unroll
            for (int c = 0; c < 4; c++) acc[a][b][c] = 0.f;

    auto fill = [&](int kt) {
        int slot = kt % NSTG;
        uint32_t sA = sbase + slot * STG_BYTES;
        uint32_t sB = sA + 16384;
#pragma unroll
        for (int t = 0; t < 4; t++) {
            int c = tid + t * 256;
            int row = c >> 3, ch = c & 7;
            int gk = kt * TK + ch * 8;
            int col = gk < ldA ? gk : gk - ldA;      // 3rd K-segment re-reads hi
            cpasync16(sA + SW128(row * 128 + ch * 16),
                      A + (size_t)(m0 + row) * ldA + col);
        }
#pragma unroll
        for (int t = 0; t < 4; t++) {
            int c = tid + t * 256;
            int row = c >> 3, ch = c & 7;
            cpasync16(sB + SW128(row * 128 + ch * 16),
                      W + (size_t)(n0 + row) * ktot + kt * TK + ch * 8);
        }
        asm volatile("cp.async.commit_group;\n");
    };

    // prologue: 2 tiles in flight
    fill(0);
    if (nK > 1) fill(1);

    const int g  = lane >> 3;     // ldmatrix address group
    const int lr = lane & 7;

    for (int kt = 0; kt < nK; kt++) {
        if (kt + 1 < nK) asm volatile("cp.async.wait_group 1;\n");
        else             asm volatile("cp.async.wait_group 0;\n");
        __syncthreads();                         // all warps done reading slot (kt+2)%3
        if (kt + 2 < nK) fill(kt + 2);           // safe: overwrites slot (kt-1)%3

        int slot = kt % NSTG;
        uint32_t sA = sbase + slot * STG_BYTES;
        uint32_t sB = sA + 16384;

#pragma unroll
        for (int ks = 0; ks < 4; ks++) {
            uint32_t a[4][4], b[2][4];
#pragma unroll
            for (int mf = 0; mf < 4; mf++) {
                int row = wm * 64 + mf * 16 + lr + ((g & 1) << 3);
                ldsm4(a[mf], sA + SW128(row * 128 + ks * 32 + ((g >> 1) << 4)));
            }
#pragma unroll
            for (int nf = 0; nf < 2; nf++) {
                int row = wn * 32 + nf * 16 + lr + ((g >> 1) << 3);
                ldsm4(b[nf], sB + SW128(row * 128 + ks * 32 + ((g & 1) << 4)));
            }
#pragma unroll
            for (int mf = 0; mf < 4; mf++) {
#pragma unroll
                for (int nf = 0; nf < 2; nf++) {
                    mma16816(acc[mf][2 * nf],     a[mf], &b[nf][0]);
                    mma16816(acc[mf][2 * nf + 1], a[mf], &b[nf][2]);
                }
            }
        }
    }

    // ------------------------- epilogue -------------------------
#pragma unroll
    for (int mt = 0; mt < 4; mt++) {
#pragma unroll
        for (int nt = 0; nt < 4; nt++) {
            int r = m0 + wm * 64 + mt * 16 + (lane >> 2);
            int n = n0 + wn * 32 + nt * 8 + (lane & 3) * 2;
            float v0 = acc[mt][nt][0], v1 = acc[mt][nt][1];
            float v2 = acc[mt][nt][2], v3 = acc[mt][nt][3];

            if (EPI == EPI_CTX) {
                outf[(size_t)r * nOut + n]           = v0 + aux[n];
                outf[(size_t)r * nOut + n + 1]       = v1 + aux[n + 1];
                outf[(size_t)(r + 8) * nOut + n]     = v2 + aux[n];
                outf[(size_t)(r + 8) * nOut + n + 1] = v3 + aux[n + 1];
            } else if (EPI == EPI_TANH_C) {
                outf[(size_t)r * nOut + n]           = tanhf(v0 + aux[n]);
                outf[(size_t)r * nOut + n + 1]       = tanhf(v1 + aux[n + 1]);
                outf[(size_t)(r + 8) * nOut + n]     = tanhf(v2 + aux[n]);
                outf[(size_t)(r + 8) * nOut + n + 1] = tanhf(v3 + aux[n + 1]);
            } else if (EPI == EPI_TANH_SPLIT) {
#pragma unroll
                for (int q = 0; q < 4; q++) {
                    int rr = (q >= 2) ? r + 8 : r;
                    int nn = n + (q & 1);
                    float v = (q == 0) ? v0 : (q == 1) ? v1 : (q == 2) ? v2 : v3;
                    float h = tanhf(v + aux[nn]);
                    __nv_bfloat16 hi = __float2bfloat16(h);
                    outs[(size_t)rr * AGLD + nn]       = hi;
                    outs[(size_t)rr * AGLD + XKG + nn] = __float2bfloat16(h - __bfloat162float(hi));
                }
            } else if (EPI == EPI_GELU) {
#pragma unroll
                for (int q = 0; q < 4; q++) {
                    int rr = (q >= 2) ? r + 8 : r;
                    int nn = n + (q & 1);
                    float v = (q == 0) ? v0 : (q == 1) ? v1 : (q == 2) ? v2 : v3;
                    float u = v + aux[nn];
                    outf[(size_t)rr * nOut + nn] = 0.5f * u * (1.f + erff(u * 0.70710678118654752f));
                }
            } else { // EPI_GATES
                float w0 = v0 + aux[(size_t)r * N4 + n];
                float w1 = v1 + aux[(size_t)r * N4 + n + 1];
                float w2 = v2 + aux[(size_t)(r + 8) * N4 + n];
                float w3 = v3 + aux[(size_t)(r + 8) * N4 + n + 1];
                float u0 = __shfl_xor_sync(0xffffffffu, w0, 1);
                float u1 = __shfl_xor_sync(0xffffffffu, w1, 1);
                float u2 = __shfl_xor_sync(0xffffffffu, w2, 1);
                float u3 = __shfl_xor_sync(0xffffffffu, w3, 1);
                if (!(lane & 1)) {  // even lanes own (i,f); partner lane^1 has (g,o)
                    int j = n >> 2;
                    lstm_cell(outf, outs, r, j, w0, w1, u0, u1);
                    lstm_cell(outf, outs, r + 8, j, w2, w3, u2, u3);
                }
            }
        }
    }
}

// ------------------------- LayerNorm (warp per row) -------------------------
__global__ void ln_kernel(const __nv_bfloat16* __restrict__ Ag,
                          const float* __restrict__ gam, const float* __restrict__ bet) {
    int warp = (blockIdx.x * blockDim.x + threadIdx.x) >> 5;
    int lane = threadIdx.x & 31;
    if (warp >= BATCH) return;
    size_t base = (size_t)warp * AGLD;
    float h[32];
    float s = 0.f, ss = 0.f;
#pragma unroll
    for (int i = 0; i < 32; i++) {
        int k = lane + 32 * i;
        float v = __bfloat162float(Ag[base + k]) + __bfloat162float(Ag[base + XKG + k]);
        h[i] = v; s += v; ss += v * v;
    }
#pragma unroll
    for (int o = 16; o; o >>= 1) {
        s  += __shfl_xor_sync(0xffffffffu, s, o);
        ss += __shfl_xor_sync(0xffffffffu, ss, o);
    }
    float mu = s * (1.f / HID);
    float var = ss * (1.f / HID) - mu * mu;
    float inv = rsqrtf(var + 1e-5f);
    size_t ob = (size_t)warp * AFLD;
#pragma unroll
    for (int i = 0; i < 32; i++) {
        int k = lane + 32 * i;
        float y = (h[i] - mu) * inv * gam[k] + bet[k];
        __nv_bfloat16 hi = __float2bfloat16(y);
        g_Af[ob + k]       = hi;
        g_Af[ob + XKF + k] = __float2bfloat16(y - __bfloat162float(hi));
    }
}

// ------------------------- delta / pos head (warp per row) -------------------------
__global__ void delta_kernel(const float* __restrict__ W2, const float* __restrict__ b2,
                             float* __restrict__ out, int t, __nv_bfloat16* __restrict__ AgN) {
    int warp = (blockIdx.x * blockDim.x + threadIdx.x) >> 5;
    int lane = threadIdx.x & 31;
    if (warp >= BATCH) return;
    const float* y = g_y2 + (size_t)warp * HID;
    float a0 = 0.f, a1 = 0.f;
#pragma unroll
    for (int i = 0; i < 32; i++) {
        int k = lane + 32 * i;
        float v = y[k];
        a0 += v * W2[k];
        a1 += v * W2[HID + k];
    }
#pragma unroll
    for (int o = 16; o; o >>= 1) {
        a0 += __shfl_xor_sync(0xffffffffu, a0, o);
        a1 += __shfl_xor_sync(0xffffffffu, a1, o);
    }
    if (lane == 0) {
        float d0 = a0 + b2[0], d1 = a1 + b2[1];
        float p0 = g_pos[warp * 2 + 0] + d0;
        float p1 = g_pos[warp * 2 + 1] + d1;
        g_pos[warp * 2 + 0] = p0;
        g_pos[warp * 2 + 1] = p1;
        out[(size_t)warp * (TSTEPS * 2) + t * 2 + 0] = p0;
        out[(size_t)warp * (TSTEPS * 2) + t * 2 + 1] = p1;
        float nn = fmaxf(sqrtf(d0 * d0 + d1 * d1), 1e-6f);
        float e[4] = {d0, d1, d0 / nn, d1 / nn};
        size_t base = (size_t)warp * AGLD;
#pragma unroll
        for (int q = 0; q < 4; q++) {
            __nv_bfloat16 hi = __float2bfloat16(e[q]);
            AgN[base + HID + q]       = hi;
            AgN[base + XKG + HID + q] = __float2bfloat16(e[q] - __bfloat162float(hi));
        }
    }
}

// ------------------------- host -------------------------
static inline int nb(long n) { return (int)((n + 255) / 256); }

extern "C" void kernel_launch(void* const* d_in, const int* in_sizes, int n_in,
                              void* d_out, int out_size) {
    const float* context    = (const float*)d_in[0];
    const float* last_pos   = (const float*)d_in[1];
    const float* last_delta = (const float*)d_in[2];
    const float* Wh   = (const float*)d_in[3];
    const float* bh   = (const float*)d_in[4];
    const float* Wc   = (const float*)d_in[5];
    const float* bc   = (const float*)d_in[6];
    const float* W_ih = (const float*)d_in[7];
    const float* b_ih = (const float*)d_in[8];
    const float* W_hh = (const float*)d_in[9];
    const float* b_hh = (const float*)d_in[10];
    const float* ln_g = (const float*)d_in[11];
    const float* ln_b = (const float*)d_in[12];
    const float* W1   = (const float*)d_in[13];
    const float* b1   = (const float*)d_in[14];
    const float* W2   = (const float*)d_in[15];
    const float* b2   = (const float*)d_in[16];
    float* out = (float*)d_out;

    __nv_bfloat16 *pCtxs, *pAg0, *pAg1, *pAf, *pWg, *pWc4, *pWhh, *pWcc, *pW1s;
    float *pGctx, *pC, *pY2, *pBsum;
    cudaGetSymbolAddress((void**)&pCtxs, g_ctxs);
    cudaGetSymbolAddress((void**)&pAg0, g_Ag0);
    cudaGetSymbolAddress((void**)&pAg1, g_Ag1);
    cudaGetSymbolAddress((void**)&pAf,  g_Af);
    cudaGetSymbolAddress((void**)&pWg,  g_Wg);
    cudaGetSymbolAddress((void**)&pWc4, g_Wc4);
    cudaGetSymbolAddress((void**)&pWhh, g_Whh);
    cudaGetSymbolAddress((void**)&pWcc, g_Wcc);
    cudaGetSymbolAddress((void**)&pW1s, g_W1s);
    cudaGetSymbolAddress((void**)&pGctx, g_gctx);
    cudaGetSymbolAddress((void**)&pC,   g_c);
    cudaGetSymbolAddress((void**)&pY2,  g_y2);
    cudaGetSymbolAddress((void**)&pBsum, g_bsum);

    cudaFuncSetAttribute(gemm2<EPI_CTX>,        cudaFuncAttributeMaxDynamicSharedMemorySize, GEMM_SMEM);
    cudaFuncSetAttribute(gemm2<EPI_TANH_SPLIT>, cudaFuncAttributeMaxDynamicSharedMemorySize, GEMM_SMEM);
    cudaFuncSetAttribute(gemm2<EPI_TANH_C>,     cudaFuncAttributeMaxDynamicSharedMemorySize, GEMM_SMEM);
    cudaFuncSetAttribute(gemm2<EPI_GATES>,      cudaFuncAttributeMaxDynamicSharedMemorySize, GEMM_SMEM);
    cudaFuncSetAttribute(gemm2<EPI_GELU>,       cudaFuncAttributeMaxDynamicSharedMemorySize, GEMM_SMEM);

    // prep
    prep_ctx_split<<<nb((long)BATCH * CTXK), 256>>>(context);
    prep_wgates<<<nb((long)N4 * XKG), 256>>>(W_hh, W_ih);
    prep_wctx<<<nb((long)N4 * XKC), 256>>>(W_ih);
    prep_bsum<<<nb(N4), 256>>>(b_ih, b_hh);
    prep_split3<<<nb((long)HID * XKC), 256>>>(Wh, pWhh, HID * XKC, XKC);
    prep_split3<<<nb((long)HID * XKC), 256>>>(Wc, pWcc, HID * XKC, XKC);
    prep_split3<<<nb((long)HID * HID), 256>>>(W1, pW1s, HID * HID, HID);
    init_misc<<<nb(BATCH), 256>>>(last_pos, last_delta);

    dim3 blk(256);
    dim3 grid_n4(N4 / 128, BATCH / 128);
    dim3 grid_h(HID / 128, BATCH / 128);

    // gates_ctx (permuted, + b_ih + b_hh), hidden/cell init
    gemm2<EPI_CTX><<<grid_n4, blk, GEMM_SMEM>>>(pCtxs, ACLD, pWc4, KC, pBsum, pGctx, nullptr, N4);
    gemm2<EPI_TANH_SPLIT><<<grid_h, blk, GEMM_SMEM>>>(pCtxs, ACLD, pWhh, KC, bh, nullptr, pAg0, HID);
    gemm2<EPI_TANH_C><<<grid_h, blk, GEMM_SMEM>>>(pCtxs, ACLD, pWcc, KC, bc, pC, nullptr, HID);

    __nv_bfloat16* Ag[2] = {pAg0, pAg1};
    for (int t = 0; t < TSTEPS; t++) {
        int cur = t & 1, nxt = cur ^ 1;
        gemm2<EPI_GATES><<<grid_n4, blk, GEMM_SMEM>>>(Ag[cur], AGLD, pWg, KG, pGctx, pC, Ag[nxt], N4);
        ln_kernel<<<BATCH / 8, 256>>>(Ag[nxt], ln_g, ln_b);
        gemm2<EPI_GELU><<<grid_h, blk, GEMM_SMEM>>>(pAf, AFLD, pW1s, KF, b1, pY2, nullptr, HID);
        delta_kernel<<<BATCH / 8, 256>>>(W2, b2, out, t, Ag[nxt]);
    }
}